// round 7
// baseline (speedup 1.0000x reference)
#include <cuda_runtime.h>
#include <cuda_bf16.h>
#include <cuda_pipeline.h>

#define N_NODES 100000
#define N_EDGES 1600000
#define NFEAT   128
#define NHID    16
#define NCLS    40
#define NSCAN_BLOCKS 196
#define GEMM_BLOCKS ((N_NODES + 255) / 256)          // 391
#define EDGE_BLOCKS ((N_EDGES / 4 + 255) / 256)      // 1563

// -------- scratch (device globals) --------
__device__ float g_p[N_NODES * 32];    // [:,0:16] = x@w_self1, [:,16:32] = x@w_neigh1
__device__ float g_h[N_NODES * 16];    // layer-1 output (post relu)
__device__ int   g_deg[N_NODES];
__device__ int   g_rowptr[N_NODES + 1];
__device__ int   g_rank[N_EDGES];      // edge's rank within its dst group
__device__ int   g_eidx[N_EDGES];      // src ids grouped by dst (CSR)
__device__ unsigned long long g_scanstate[NSCAN_BLOCKS];  // flag(hi32) | value(lo32)

// -------- count in-degrees + per-edge rank; zero scan state --------
__global__ void k_count(const int* __restrict__ dst) {
    if (blockIdx.x == 0 && threadIdx.x < NSCAN_BLOCKS)
        *(volatile unsigned long long*)&g_scanstate[threadIdx.x] = 0ULL;
    int e = blockIdx.x * blockDim.x + threadIdx.x;
    if (e * 4 < N_EDGES) {
        int4 d = ((const int4*)dst)[e];
        int4 r;
        r.x = atomicAdd(&g_deg[d.x], 1);
        r.y = atomicAdd(&g_deg[d.y], 1);
        r.z = atomicAdd(&g_deg[d.z], 1);
        r.w = atomicAdd(&g_deg[d.w], 1);
        ((int4*)g_rank)[e] = r;
    }
}

__device__ __forceinline__ int warp_sum(int v) {
#pragma unroll
    for (int o = 16; o; o >>= 1) v += __shfl_xor_sync(0xffffffffu, v, o);
    return v;
}

// -------- single-pass exclusive scan over g_deg (decoupled lookback) --------
__global__ void __launch_bounds__(512) k_scan() {
    __shared__ int s[512];
    __shared__ int s_prev;
    int b = blockIdx.x, t = threadIdx.x;
    int i = b * 512 + t;
    int v = (i < N_NODES) ? g_deg[i] : 0;
    s[t] = v;
    __syncthreads();
#pragma unroll
    for (int off = 1; off < 512; off <<= 1) {
        int tv = (t >= off) ? s[t - off] : 0;
        __syncthreads();
        s[t] += tv;
        __syncthreads();
    }
    int incl = s[t];
    int blocksum = s[511];

    if (t == 0) {
        unsigned long long pkg = ((b == 0) ? (2ULL << 32) : (1ULL << 32))
                               | (unsigned int)blocksum;
        *(volatile unsigned long long*)&g_scanstate[b] = pkg;
    }

    if (t < 32) {
        int prefix = 0;
        int look = b - 1;
        while (look >= 0) {
            int idx = look - t;
            unsigned long long st = (idx >= 0)
                ? *(volatile unsigned long long*)&g_scanstate[idx]
                : (2ULL << 32);
            unsigned int flag = (unsigned int)(st >> 32);
            int val = (int)(st & 0xffffffffu);
            unsigned int nr = __ballot_sync(0xffffffffu, flag == 0u);
            unsigned int pm = __ballot_sync(0xffffffffu, flag == 2u);
            int firstP = pm ? (__ffs(pm) - 1) : 32;
            unsigned int below = (firstP < 32) ? ((1u << firstP) - 1u) : 0xffffffffu;
            if (firstP < 32 && (nr & below) == 0u) {
                int c = (t <= firstP) ? val : 0;
                prefix += warp_sum(c);
                break;
            } else if (nr == 0u) {
                prefix += warp_sum(val);
                look -= 32;
            }
        }
        if (t == 0) {
            s_prev = prefix;
            *(volatile unsigned long long*)&g_scanstate[b] =
                (2ULL << 32) | (unsigned int)(prefix + blocksum);
        }
    }
    __syncthreads();
    int base = s_prev;
    if (i < N_NODES)
        g_rowptr[i] = base + incl - v;
    if (b == NSCAN_BLOCKS - 1 && t == 511)
        g_rowptr[N_NODES] = base + incl;
}

// -------- fill: pos = rowptr[dst] + rank  (no atomics) --------
__global__ void k_fill(const int* __restrict__ src, const int* __restrict__ dst) {
    int e = blockIdx.x * blockDim.x + threadIdx.x;
    if (e * 4 < N_EDGES) {
        int4 s4 = ((const int4*)src)[e];
        int4 d4 = ((const int4*)dst)[e];
        int4 r4 = ((const int4*)g_rank)[e];
        g_eidx[__ldg(&g_rowptr[d4.x]) + r4.x] = s4.x;
        g_eidx[__ldg(&g_rowptr[d4.y]) + r4.y] = s4.y;
        g_eidx[__ldg(&g_rowptr[d4.z]) + r4.z] = s4.z;
        g_eidx[__ldg(&g_rowptr[d4.w]) + r4.w] = s4.w;
    }
}

// ===================== GEMM1 (runs on side stream, hidden under CSR build) ===
// p = x @ [w_self1 | w_neigh1]   (100000 x 128) @ (128 x 32)
#define XS_STRIDE 36

__device__ __forceinline__ void ffma2(unsigned long long& acc,
                                      unsigned long long a,
                                      unsigned long long b) {
    asm("fma.rn.f32x2 %0, %1, %2, %0;" : "+l"(acc) : "l"(a), "l"(b));
}

__global__ void __launch_bounds__(256, 2) k_gemm1(const float* __restrict__ x,
                                                  const float* __restrict__ wn1,
                                                  const float* __restrict__ ws1) {
    __shared__ __align__(16) float xs[256 * XS_STRIDE];   // 36 KB
    __shared__ __align__(16) float wt2[4096];             // 16 KB
    int tid = threadIdx.x;
    int row0 = blockIdx.x * 256;

    // pack weights: wt2[k4g*128 + c*16 + cg*4 + j] = W[k4g*4+j][cg*8+c]
    for (int i = tid; i < 4096; i += 256) {
        int j   = i & 3;
        int cg  = (i >> 2) & 3;
        int c   = (i >> 4) & 7;
        int k4g = i >> 7;
        int col = cg * 8 + c;
        int k   = k4g * 4 + j;
        wt2[i] = (col < 16) ? ws1[k * 16 + col] : wn1[k * 16 + (col - 16)];
    }

    int cg = tid & 3;        // col group (0..3), 8 cols each
    int rg = tid >> 2;       // row group (0..63), rows rg + q*64

    unsigned long long acc[4][8];
#pragma unroll
    for (int q = 0; q < 4; q++)
#pragma unroll
        for (int c = 0; c < 8; c++) acc[q][c] = 0ULL;

#pragma unroll
    for (int chunk = 0; chunk < 4; chunk++) {
        __syncthreads();
#pragma unroll
        for (int l = 0; l < 8; l++) {
            int f = l * 256 + tid;
            int row = f >> 3, slot = f & 7;
            int gr = row0 + row;
            if (gr >= N_NODES) gr = N_NODES - 1;   // clamp; stores guarded
            __pipeline_memcpy_async(&xs[row * XS_STRIDE + slot * 4],
                                    &x[gr * 128 + chunk * 32 + slot * 4], 16);
        }
        __pipeline_commit();
        __pipeline_wait_prior(0);
        __syncthreads();

#pragma unroll
        for (int k4 = 0; k4 < 8; k4++) {
            int k4g = chunk * 8 + k4;
            const float* wbase = wt2 + k4g * 128 + cg * 4;
            ulonglong2 xv[4];
#pragma unroll
            for (int q = 0; q < 4; q++)
                xv[q] = *(const ulonglong2*)&xs[(rg + q * 64) * XS_STRIDE + k4 * 4];
#pragma unroll
            for (int ch = 0; ch < 2; ch++) {
                ulonglong2 wv[4];
#pragma unroll
                for (int c = 0; c < 4; c++)
                    wv[c] = *(const ulonglong2*)(wbase + (ch * 4 + c) * 16);
#pragma unroll
                for (int q = 0; q < 4; q++)
#pragma unroll
                    for (int c = 0; c < 4; c++)
                        ffma2(acc[q][ch * 4 + c], xv[q].x, wv[c].x);
#pragma unroll
                for (int q = 0; q < 4; q++)
#pragma unroll
                    for (int c = 0; c < 4; c++)
                        ffma2(acc[q][ch * 4 + c], xv[q].y, wv[c].y);
            }
        }
    }

#pragma unroll
    for (int q = 0; q < 4; q++) {
        int gr = row0 + rg + q * 64;
        if (gr < N_NODES) {
            float o[8];
#pragma unroll
            for (int c = 0; c < 8; c++) {
                float2 a = *(float2*)&acc[q][c];
                o[c] = a.x + a.y;
            }
            *(float4*)(&g_p[gr * 32 + cg * 8])     = make_float4(o[0], o[1], o[2], o[3]);
            *(float4*)(&g_p[gr * 32 + cg * 8 + 4]) = make_float4(o[4], o[5], o[6], o[7]);
        }
    }
}

// -------- layer-1 aggregate + combine + relu --------
__global__ void __launch_bounds__(256) k_agg1(const float* __restrict__ b1) {
    int t = blockIdx.x * blockDim.x + threadIdx.x;
    int n = t >> 2;
    int fq = t & 3;
    if (n >= N_NODES) return;
    int beg = g_rowptr[n];
    int end = g_rowptr[n + 1];
    float4 acc = make_float4(0.f, 0.f, 0.f, 0.f);
    int i = beg;
    for (; i + 4 <= end; i += 4) {
        int s0 = g_eidx[i], s1 = g_eidx[i + 1], s2 = g_eidx[i + 2], s3 = g_eidx[i + 3];
        float4 v0 = *(const float4*)&g_p[s0 * 32 + 16 + fq * 4];
        float4 v1 = *(const float4*)&g_p[s1 * 32 + 16 + fq * 4];
        float4 v2 = *(const float4*)&g_p[s2 * 32 + 16 + fq * 4];
        float4 v3 = *(const float4*)&g_p[s3 * 32 + 16 + fq * 4];
        acc.x += (v0.x + v1.x) + (v2.x + v3.x);
        acc.y += (v0.y + v1.y) + (v2.y + v3.y);
        acc.z += (v0.z + v1.z) + (v2.z + v3.z);
        acc.w += (v0.w + v1.w) + (v2.w + v3.w);
    }
    for (; i < end; i++) {
        int s = g_eidx[i];
        float4 v = *(const float4*)&g_p[s * 32 + 16 + fq * 4];
        acc.x += v.x; acc.y += v.y; acc.z += v.z; acc.w += v.w;
    }
    float inv = 1.f / fmaxf((float)(end - beg), 1.f);
    float4 self = *(const float4*)&g_p[n * 32 + fq * 4];
    float4 bb = *(const float4*)&b1[fq * 4];
    float4 o;
    o.x = fmaxf(self.x + acc.x * inv + bb.x, 0.f);
    o.y = fmaxf(self.y + acc.y * inv + bb.y, 0.f);
    o.z = fmaxf(self.z + acc.z * inv + bb.z, 0.f);
    o.w = fmaxf(self.w + acc.w * inv + bb.w, 0.f);
    *(float4*)&g_h[n * 16 + fq * 4] = o;
}

// -------- fused layer-2 aggregate + output projection --------
__global__ void __launch_bounds__(256) k_agg2out(const float* __restrict__ wn2,
                                                 const float* __restrict__ ws2,
                                                 const float* __restrict__ b2,
                                                 float* __restrict__ out) {
    __shared__ float sw[2 * 640];
    __shared__ float sb[40];
    __shared__ float4 sh4[64 * 4];
    __shared__ float4 sm4[64 * 4];
    int t = threadIdx.x;
    for (int i = t; i < 640; i += 256) { sw[i] = ws2[i]; sw[640 + i] = wn2[i]; }
    if (t < 40) sb[t] = b2[t];

    int n0 = blockIdx.x * 64;
    int nl = t >> 2, fq = t & 3;
    int n = n0 + nl;
    float4 acc = make_float4(0.f, 0.f, 0.f, 0.f);
    float4 hv = make_float4(0.f, 0.f, 0.f, 0.f);
    if (n < N_NODES) {
        int beg = g_rowptr[n];
        int end = g_rowptr[n + 1];
        int i = beg;
        for (; i + 4 <= end; i += 4) {
            int s0 = g_eidx[i], s1 = g_eidx[i + 1], s2 = g_eidx[i + 2], s3 = g_eidx[i + 3];
            float4 v0 = *(const float4*)&g_h[s0 * 16 + fq * 4];
            float4 v1 = *(const float4*)&g_h[s1 * 16 + fq * 4];
            float4 v2 = *(const float4*)&g_h[s2 * 16 + fq * 4];
            float4 v3 = *(const float4*)&g_h[s3 * 16 + fq * 4];
            acc.x += (v0.x + v1.x) + (v2.x + v3.x);
            acc.y += (v0.y + v1.y) + (v2.y + v3.y);
            acc.z += (v0.z + v1.z) + (v2.z + v3.z);
            acc.w += (v0.w + v1.w) + (v2.w + v3.w);
        }
        for (; i < end; i++) {
            int s = g_eidx[i];
            float4 v = *(const float4*)&g_h[s * 16 + fq * 4];
            acc.x += v.x; acc.y += v.y; acc.z += v.z; acc.w += v.w;
        }
        float inv = 1.f / fmaxf((float)(end - beg), 1.f);
        acc.x *= inv; acc.y *= inv; acc.z *= inv; acc.w *= inv;
        hv = *(const float4*)&g_h[n * 16 + fq * 4];
    }
    sh4[nl * 4 + fq] = hv;
    sm4[nl * 4 + fq] = acc;
    __syncthreads();

    const float* shf = (const float*)sh4;
    const float* smf = (const float*)sm4;
#pragma unroll
    for (int o = t; o < 64 * 40; o += 256) {
        int n2 = o / 40, c = o % 40;
        int gn = n0 + n2;
        if (gn < N_NODES) {
            float a = sb[c];
#pragma unroll
            for (int k = 0; k < 16; k++)
                a += shf[n2 * 16 + k] * sw[k * 40 + c]
                   + smf[n2 * 16 + k] * sw[640 + k * 40 + c];
            out[gn * 40 + c] = a;
        }
    }
}

extern "C" void kernel_launch(void* const* d_in, const int* in_sizes, int n_in,
                              void* d_out, int out_size) {
    const float* x   = (const float*)d_in[0];
    const int*   src = (const int*)d_in[1];
    const int*   dst = (const int*)d_in[2];
    const float* wn1 = (const float*)d_in[3];
    const float* ws1 = (const float*)d_in[4];
    const float* b1  = (const float*)d_in[5];
    const float* wn2 = (const float*)d_in[6];
    const float* ws2 = (const float*)d_in[7];
    const float* b2  = (const float*)d_in[8];
    float* out = (float*)d_out;

    // host-side resources, created once; each call records the identical DAG
    static cudaStream_t s1 = nullptr;
    static cudaEvent_t ev_fork = nullptr, ev_join = nullptr;
    if (s1 == nullptr) {
        cudaStreamCreateWithFlags(&s1, cudaStreamNonBlocking);
        cudaEventCreateWithFlags(&ev_fork, cudaEventDisableTiming);
        cudaEventCreateWithFlags(&ev_join, cudaEventDisableTiming);
    }

    void* degp = nullptr;
    cudaGetSymbolAddress(&degp, g_deg);

    // fork: gemm1 on s1 runs concurrently with the CSR build chain
    cudaEventRecord(ev_fork, 0);
    cudaStreamWaitEvent(s1, ev_fork, 0);

    cudaMemsetAsync(degp, 0, N_NODES * sizeof(int));          // default stream
    k_count<<<EDGE_BLOCKS, 256>>>(dst);                        // kernel idx 0
    k_scan<<<NSCAN_BLOCKS, 512>>>();                           // idx 1
    k_fill<<<EDGE_BLOCKS, 256>>>(src, dst);                    // idx 2

    k_gemm1<<<GEMM_BLOCKS, 256, 0, s1>>>(x, wn1, ws1);         // idx 3 -> profiled

    // join: agg1 needs both CSR (default stream) and g_p (s1)
    cudaEventRecord(ev_join, s1);
    cudaStreamWaitEvent(0, ev_join, 0);

    k_agg1<<<(N_NODES * 4 + 255) / 256, 256>>>(b1);
    k_agg2out<<<(N_NODES + 63) / 64, 256>>>(wn2, ws2, b2, out);
}

// round 8
// speedup vs baseline: 1.0754x; 1.0754x over previous
#include <cuda_runtime.h>
#include <cuda_bf16.h>
#include <cuda_pipeline.h>

#define N_NODES 100000
#define N_EDGES 1600000
#define NFEAT   128
#define NHID    16
#define NCLS    40
#define NSCAN_BLOCKS 196
#define GEMM_BLOCKS ((N_NODES + 255) / 256)          // 391
#define EDGE_BLOCKS ((N_EDGES / 8 + 255) / 256)      // 782 (8 edges/thread)

// -------- scratch (device globals) --------
__device__ float g_p[N_NODES * 32];    // [:,0:16] = x@w_self1, [:,16:32] = x@w_neigh1
__device__ float g_h[N_NODES * 16];    // layer-1 output (post relu)
__device__ int   g_deg[N_NODES];
__device__ int   g_rowptr[N_NODES + 1];
__device__ int   g_rank[N_EDGES];      // edge's rank within its dst group
__device__ int   g_eidx[N_EDGES];      // src ids grouped by dst (CSR)
__device__ unsigned long long g_scanstate[NSCAN_BLOCKS];  // flag(hi32) | value(lo32)

// ===================== fused GEMM1 + degree count =====================
#define XS_STRIDE 36

__device__ __forceinline__ void ffma2(unsigned long long& acc,
                                      unsigned long long a,
                                      unsigned long long b) {
    asm("fma.rn.f32x2 %0, %1, %2, %0;" : "+l"(acc) : "l"(a), "l"(b));
}

__global__ void __launch_bounds__(256, 3) k_gemm_count(const float* __restrict__ x,
                                                       const float* __restrict__ wn1,
                                                       const float* __restrict__ ws1,
                                                       const int* __restrict__ dst) {
    __shared__ __align__(16) float xs[256 * XS_STRIDE];   // 36 KB
    __shared__ __align__(16) float wt2[4096];             // 16 KB
    int tid = threadIdx.x;

    if (blockIdx.x >= GEMM_BLOCKS) {
        // ---- count branch: 8 edges/thread ----
        int cb = blockIdx.x - GEMM_BLOCKS;
        if (cb == 0 && tid < NSCAN_BLOCKS)
            *(volatile unsigned long long*)&g_scanstate[tid] = 0ULL;
        int e = cb * 256 + tid;          // int4-pair index
#pragma unroll
        for (int h = 0; h < 2; h++) {
            int e4 = e * 2 + h;
            if (e4 * 4 < N_EDGES) {
                int4 d = ((const int4*)dst)[e4];
                int4 r;
                r.x = atomicAdd(&g_deg[d.x], 1);
                r.y = atomicAdd(&g_deg[d.y], 1);
                r.z = atomicAdd(&g_deg[d.z], 1);
                r.w = atomicAdd(&g_deg[d.w], 1);
                ((int4*)g_rank)[e4] = r;
            }
        }
        return;
    }

    // ---- gemm branch ----
    int row0 = blockIdx.x * 256;

    // pack weights: wt2[k4g*128 + c*16 + cg*4 + j] = W[k4g*4+j][cg*8+c]
    for (int i = tid; i < 4096; i += 256) {
        int j   = i & 3;
        int cg  = (i >> 2) & 3;
        int c   = (i >> 4) & 7;
        int k4g = i >> 7;
        int col = cg * 8 + c;
        int k   = k4g * 4 + j;
        wt2[i] = (col < 16) ? ws1[k * 16 + col] : wn1[k * 16 + (col - 16)];
    }

    int cg = tid & 3;        // col group (0..3), 8 cols each
    int rg = tid >> 2;       // row group (0..63), rows rg + q*64

    unsigned long long acc[4][8];
#pragma unroll
    for (int q = 0; q < 4; q++)
#pragma unroll
        for (int c = 0; c < 8; c++) acc[q][c] = 0ULL;

#pragma unroll
    for (int chunk = 0; chunk < 4; chunk++) {
        __syncthreads();
#pragma unroll
        for (int l = 0; l < 8; l++) {
            int f = l * 256 + tid;
            int row = f >> 3, slot = f & 7;
            int gr = row0 + row;
            if (gr >= N_NODES) gr = N_NODES - 1;   // clamp; stores guarded
            __pipeline_memcpy_async(&xs[row * XS_STRIDE + slot * 4],
                                    &x[gr * 128 + chunk * 32 + slot * 4], 16);
        }
        __pipeline_commit();
        __pipeline_wait_prior(0);
        __syncthreads();

#pragma unroll
        for (int k4 = 0; k4 < 8; k4++) {
            int k4g = chunk * 8 + k4;
            const float* wbase = wt2 + k4g * 128 + cg * 4;
            ulonglong2 xv[4];
#pragma unroll
            for (int q = 0; q < 4; q++)
                xv[q] = *(const ulonglong2*)&xs[(rg + q * 64) * XS_STRIDE + k4 * 4];
#pragma unroll
            for (int ch = 0; ch < 2; ch++) {
                ulonglong2 wv[4];
#pragma unroll
                for (int c = 0; c < 4; c++)
                    wv[c] = *(const ulonglong2*)(wbase + (ch * 4 + c) * 16);
#pragma unroll
                for (int q = 0; q < 4; q++)
#pragma unroll
                    for (int c = 0; c < 4; c++)
                        ffma2(acc[q][ch * 4 + c], xv[q].x, wv[c].x);
#pragma unroll
                for (int q = 0; q < 4; q++)
#pragma unroll
                    for (int c = 0; c < 4; c++)
                        ffma2(acc[q][ch * 4 + c], xv[q].y, wv[c].y);
            }
        }
    }

#pragma unroll
    for (int q = 0; q < 4; q++) {
        int gr = row0 + rg + q * 64;
        if (gr < N_NODES) {
            float o[8];
#pragma unroll
            for (int c = 0; c < 8; c++) {
                float2 a = *(float2*)&acc[q][c];
                o[c] = a.x + a.y;
            }
            *(float4*)(&g_p[gr * 32 + cg * 8])     = make_float4(o[0], o[1], o[2], o[3]);
            *(float4*)(&g_p[gr * 32 + cg * 8 + 4]) = make_float4(o[4], o[5], o[6], o[7]);
        }
    }
}

__device__ __forceinline__ int warp_sum(int v) {
#pragma unroll
    for (int o = 16; o; o >>= 1) v += __shfl_xor_sync(0xffffffffu, v, o);
    return v;
}

// -------- single-pass exclusive scan over g_deg (decoupled lookback) --------
__global__ void __launch_bounds__(512) k_scan() {
    __shared__ int s[512];
    __shared__ int s_prev;
    int b = blockIdx.x, t = threadIdx.x;
    int i = b * 512 + t;
    int v = (i < N_NODES) ? g_deg[i] : 0;
    s[t] = v;
    __syncthreads();
#pragma unroll
    for (int off = 1; off < 512; off <<= 1) {
        int tv = (t >= off) ? s[t - off] : 0;
        __syncthreads();
        s[t] += tv;
        __syncthreads();
    }
    int incl = s[t];
    int blocksum = s[511];

    if (t == 0) {
        unsigned long long pkg = ((b == 0) ? (2ULL << 32) : (1ULL << 32))
                               | (unsigned int)blocksum;
        *(volatile unsigned long long*)&g_scanstate[b] = pkg;
    }

    if (t < 32) {
        int prefix = 0;
        int look = b - 1;
        while (look >= 0) {
            int idx = look - t;
            unsigned long long st = (idx >= 0)
                ? *(volatile unsigned long long*)&g_scanstate[idx]
                : (2ULL << 32);
            unsigned int flag = (unsigned int)(st >> 32);
            int val = (int)(st & 0xffffffffu);
            unsigned int nr = __ballot_sync(0xffffffffu, flag == 0u);
            unsigned int pm = __ballot_sync(0xffffffffu, flag == 2u);
            int firstP = pm ? (__ffs(pm) - 1) : 32;
            unsigned int below = (firstP < 32) ? ((1u << firstP) - 1u) : 0xffffffffu;
            if (firstP < 32 && (nr & below) == 0u) {
                int c = (t <= firstP) ? val : 0;
                prefix += warp_sum(c);
                break;
            } else if (nr == 0u) {
                prefix += warp_sum(val);
                look -= 32;
            }
        }
        if (t == 0) {
            s_prev = prefix;
            *(volatile unsigned long long*)&g_scanstate[b] =
                (2ULL << 32) | (unsigned int)(prefix + blocksum);
        }
    }
    __syncthreads();
    int base = s_prev;
    if (i < N_NODES)
        g_rowptr[i] = base + incl - v;
    if (b == NSCAN_BLOCKS - 1 && t == 511)
        g_rowptr[N_NODES] = base + incl;
}

// -------- fill: pos = rowptr[dst] + rank  (no atomics); 8 edges/thread ------
__global__ void k_fill(const int* __restrict__ src, const int* __restrict__ dst) {
    int e = blockIdx.x * blockDim.x + threadIdx.x;
#pragma unroll
    for (int h = 0; h < 2; h++) {
        int e4 = e * 2 + h;
        if (e4 * 4 < N_EDGES) {
            int4 s4 = ((const int4*)src)[e4];
            int4 d4 = ((const int4*)dst)[e4];
            int4 r4 = ((const int4*)g_rank)[e4];
            g_eidx[__ldg(&g_rowptr[d4.x]) + r4.x] = s4.x;
            g_eidx[__ldg(&g_rowptr[d4.y]) + r4.y] = s4.y;
            g_eidx[__ldg(&g_rowptr[d4.z]) + r4.z] = s4.z;
            g_eidx[__ldg(&g_rowptr[d4.w]) + r4.w] = s4.w;
        }
    }
}

// -------- layer-1 aggregate + combine + relu (8-wide unroll, 2 acc sets) ----
__global__ void __launch_bounds__(256) k_agg1(const float* __restrict__ b1) {
    int t = blockIdx.x * blockDim.x + threadIdx.x;
    int n = t >> 2;
    int fq = t & 3;
    if (n >= N_NODES) return;
    int beg = g_rowptr[n];
    int end = g_rowptr[n + 1];
    float4 acc = make_float4(0.f, 0.f, 0.f, 0.f);
    float4 acd = make_float4(0.f, 0.f, 0.f, 0.f);
    int i = beg;
    for (; i + 8 <= end; i += 8) {
        int s0 = g_eidx[i],     s1 = g_eidx[i + 1], s2 = g_eidx[i + 2], s3 = g_eidx[i + 3];
        int s4 = g_eidx[i + 4], s5 = g_eidx[i + 5], s6 = g_eidx[i + 6], s7 = g_eidx[i + 7];
        float4 v0 = *(const float4*)&g_p[s0 * 32 + 16 + fq * 4];
        float4 v1 = *(const float4*)&g_p[s1 * 32 + 16 + fq * 4];
        float4 v2 = *(const float4*)&g_p[s2 * 32 + 16 + fq * 4];
        float4 v3 = *(const float4*)&g_p[s3 * 32 + 16 + fq * 4];
        float4 v4 = *(const float4*)&g_p[s4 * 32 + 16 + fq * 4];
        float4 v5 = *(const float4*)&g_p[s5 * 32 + 16 + fq * 4];
        float4 v6 = *(const float4*)&g_p[s6 * 32 + 16 + fq * 4];
        float4 v7 = *(const float4*)&g_p[s7 * 32 + 16 + fq * 4];
        acc.x += (v0.x + v1.x) + (v2.x + v3.x);
        acc.y += (v0.y + v1.y) + (v2.y + v3.y);
        acc.z += (v0.z + v1.z) + (v2.z + v3.z);
        acc.w += (v0.w + v1.w) + (v2.w + v3.w);
        acd.x += (v4.x + v5.x) + (v6.x + v7.x);
        acd.y += (v4.y + v5.y) + (v6.y + v7.y);
        acd.z += (v4.z + v5.z) + (v6.z + v7.z);
        acd.w += (v4.w + v5.w) + (v6.w + v7.w);
    }
    for (; i < end; i++) {
        int s = g_eidx[i];
        float4 v = *(const float4*)&g_p[s * 32 + 16 + fq * 4];
        acc.x += v.x; acc.y += v.y; acc.z += v.z; acc.w += v.w;
    }
    acc.x += acd.x; acc.y += acd.y; acc.z += acd.z; acc.w += acd.w;
    float inv = 1.f / fmaxf((float)(end - beg), 1.f);
    float4 self = *(const float4*)&g_p[n * 32 + fq * 4];
    float4 bb = *(const float4*)&b1[fq * 4];
    float4 o;
    o.x = fmaxf(self.x + acc.x * inv + bb.x, 0.f);
    o.y = fmaxf(self.y + acc.y * inv + bb.y, 0.f);
    o.z = fmaxf(self.z + acc.z * inv + bb.z, 0.f);
    o.w = fmaxf(self.w + acc.w * inv + bb.w, 0.f);
    *(float4*)&g_h[n * 16 + fq * 4] = o;
}

// -------- fused layer-2 aggregate + output projection --------
__global__ void __launch_bounds__(256) k_agg2out(const float* __restrict__ wn2,
                                                 const float* __restrict__ ws2,
                                                 const float* __restrict__ b2,
                                                 float* __restrict__ out) {
    __shared__ float sw[2 * 640];
    __shared__ float sb[40];
    __shared__ float4 sh4[64 * 4];
    __shared__ float4 sm4[64 * 4];
    int t = threadIdx.x;
    for (int i = t; i < 640; i += 256) { sw[i] = ws2[i]; sw[640 + i] = wn2[i]; }
    if (t < 40) sb[t] = b2[t];

    int n0 = blockIdx.x * 64;
    int nl = t >> 2, fq = t & 3;
    int n = n0 + nl;
    float4 acc = make_float4(0.f, 0.f, 0.f, 0.f);
    float4 hv = make_float4(0.f, 0.f, 0.f, 0.f);
    if (n < N_NODES) {
        int beg = g_rowptr[n];
        int end = g_rowptr[n + 1];
        float4 acd = make_float4(0.f, 0.f, 0.f, 0.f);
        int i = beg;
        for (; i + 8 <= end; i += 8) {
            int s0 = g_eidx[i],     s1 = g_eidx[i + 1], s2 = g_eidx[i + 2], s3 = g_eidx[i + 3];
            int s4 = g_eidx[i + 4], s5 = g_eidx[i + 5], s6 = g_eidx[i + 6], s7 = g_eidx[i + 7];
            float4 v0 = *(const float4*)&g_h[s0 * 16 + fq * 4];
            float4 v1 = *(const float4*)&g_h[s1 * 16 + fq * 4];
            float4 v2 = *(const float4*)&g_h[s2 * 16 + fq * 4];
            float4 v3 = *(const float4*)&g_h[s3 * 16 + fq * 4];
            float4 v4 = *(const float4*)&g_h[s4 * 16 + fq * 4];
            float4 v5 = *(const float4*)&g_h[s5 * 16 + fq * 4];
            float4 v6 = *(const float4*)&g_h[s6 * 16 + fq * 4];
            float4 v7 = *(const float4*)&g_h[s7 * 16 + fq * 4];
            acc.x += (v0.x + v1.x) + (v2.x + v3.x);
            acc.y += (v0.y + v1.y) + (v2.y + v3.y);
            acc.z += (v0.z + v1.z) + (v2.z + v3.z);
            acc.w += (v0.w + v1.w) + (v2.w + v3.w);
            acd.x += (v4.x + v5.x) + (v6.x + v7.x);
            acd.y += (v4.y + v5.y) + (v6.y + v7.y);
            acd.z += (v4.z + v5.z) + (v6.z + v7.z);
            acd.w += (v4.w + v5.w) + (v6.w + v7.w);
        }
        for (; i < end; i++) {
            int s = g_eidx[i];
            float4 v = *(const float4*)&g_h[s * 16 + fq * 4];
            acc.x += v.x; acc.y += v.y; acc.z += v.z; acc.w += v.w;
        }
        acc.x += acd.x; acc.y += acd.y; acc.z += acd.z; acc.w += acd.w;
        float inv = 1.f / fmaxf((float)(end - beg), 1.f);
        acc.x *= inv; acc.y *= inv; acc.z *= inv; acc.w *= inv;
        hv = *(const float4*)&g_h[n * 16 + fq * 4];
    }
    sh4[nl * 4 + fq] = hv;
    sm4[nl * 4 + fq] = acc;
    __syncthreads();

    const float* shf = (const float*)sh4;
    const float* smf = (const float*)sm4;
#pragma unroll
    for (int o = t; o < 64 * 40; o += 256) {
        int n2 = o / 40, c = o % 40;
        int gn = n0 + n2;
        if (gn < N_NODES) {
            float a = sb[c];
#pragma unroll
            for (int k = 0; k < 16; k++)
                a += shf[n2 * 16 + k] * sw[k * 40 + c]
                   + smf[n2 * 16 + k] * sw[640 + k * 40 + c];
            out[gn * 40 + c] = a;
        }
    }
}

extern "C" void kernel_launch(void* const* d_in, const int* in_sizes, int n_in,
                              void* d_out, int out_size) {
    const float* x   = (const float*)d_in[0];
    const int*   src = (const int*)d_in[1];
    const int*   dst = (const int*)d_in[2];
    const float* wn1 = (const float*)d_in[3];
    const float* ws1 = (const float*)d_in[4];
    const float* b1  = (const float*)d_in[5];
    const float* wn2 = (const float*)d_in[6];
    const float* ws2 = (const float*)d_in[7];
    const float* b2  = (const float*)d_in[8];
    float* out = (float*)d_out;

    void* degp = nullptr;
    cudaGetSymbolAddress(&degp, g_deg);
    cudaMemsetAsync(degp, 0, N_NODES * sizeof(int));

    k_gemm_count<<<GEMM_BLOCKS + EDGE_BLOCKS, 256>>>(x, wn1, ws1, dst);   // idx 0
    k_scan<<<NSCAN_BLOCKS, 512>>>();                                      // idx 1
    k_fill<<<EDGE_BLOCKS, 256>>>(src, dst);                               // idx 2
    k_agg1<<<(N_NODES * 4 + 255) / 256, 256>>>(b1);                       // idx 3 -> profiled
    k_agg2out<<<(N_NODES + 63) / 64, 256>>>(wn2, ws2, b2, out);           // idx 4
}

// round 9
// speedup vs baseline: 1.4096x; 1.3107x over previous
#include <cuda_runtime.h>
#include <cuda_bf16.h>
#include <cuda_pipeline.h>

#define N_NODES 100000
#define N_EDGES 1600000
#define NFEAT   128
#define NHID    16
#define NCLS    40
#define NSCAN_BLOCKS 196
#define GEMM_BLOCKS ((N_NODES + 255) / 256)          // 391
#define EDGE_BLOCKS ((N_EDGES / 4 + 255) / 256)      // 1563

// -------- scratch (device globals; zero-initialized at module load) --------
__device__ float g_p[N_NODES * 32];    // [:,0:16] = x@w_self1, [:,16:32] = x@w_neigh1
__device__ float g_h[N_NODES * 16];    // layer-1 output (post relu)
__device__ int   g_deg[N_NODES];       // INVARIANT: zero at entry/exit of each call
__device__ int   g_rowptr[N_NODES + 1];
__device__ int   g_rank[N_EDGES];      // edge's rank within its dst group
__device__ int   g_eidx[N_EDGES];      // src ids grouped by dst (CSR)
__device__ unsigned long long g_scanstate[NSCAN_BLOCKS];  // flag(hi32) | value(lo32)

// ===================== fused GEMM1 + degree count =====================
// blocks [0, GEMM_BLOCKS): p = x @ [w_self1 | w_neigh1]  (100000x128)@(128x32)
// blocks [GEMM_BLOCKS, +EDGE_BLOCKS): count in-degrees + per-edge rank.
#define XS_STRIDE 36

__device__ __forceinline__ void ffma2(unsigned long long& acc,
                                      unsigned long long a,
                                      unsigned long long b) {
    asm("fma.rn.f32x2 %0, %1, %2, %0;" : "+l"(acc) : "l"(a), "l"(b));
}

__global__ void __launch_bounds__(256, 2) k_gemm_count(const float* __restrict__ x,
                                                       const float* __restrict__ wn1,
                                                       const float* __restrict__ ws1,
                                                       const int* __restrict__ dst) {
    __shared__ __align__(16) float xs[256 * XS_STRIDE];   // 36 KB
    __shared__ __align__(16) float wt2[4096];             // 16 KB
    int tid = threadIdx.x;

    if (blockIdx.x >= GEMM_BLOCKS) {
        // ---- count branch ----
        int cb = blockIdx.x - GEMM_BLOCKS;
        if (cb == 0 && tid < NSCAN_BLOCKS)
            *(volatile unsigned long long*)&g_scanstate[tid] = 0ULL;
        int e = cb * 256 + tid;
        if (e * 4 < N_EDGES) {
            int4 d = ((const int4*)dst)[e];
            int4 r;
            r.x = atomicAdd(&g_deg[d.x], 1);
            r.y = atomicAdd(&g_deg[d.y], 1);
            r.z = atomicAdd(&g_deg[d.z], 1);
            r.w = atomicAdd(&g_deg[d.w], 1);
            ((int4*)g_rank)[e] = r;
        }
        return;
    }

    // ---- gemm branch ----
    int row0 = blockIdx.x * 256;

    // pack weights: wt2[k4g*128 + c*16 + cg*4 + j] = W[k4g*4+j][cg*8+c]
    for (int i = tid; i < 4096; i += 256) {
        int j   = i & 3;
        int cg  = (i >> 2) & 3;
        int c   = (i >> 4) & 7;
        int k4g = i >> 7;
        int col = cg * 8 + c;
        int k   = k4g * 4 + j;
        wt2[i] = (col < 16) ? ws1[k * 16 + col] : wn1[k * 16 + (col - 16)];
    }

    int cg = tid & 3;        // col group (0..3), 8 cols each
    int rg = tid >> 2;       // row group (0..63), rows rg + q*64

    unsigned long long acc[4][8];
#pragma unroll
    for (int q = 0; q < 4; q++)
#pragma unroll
        for (int c = 0; c < 8; c++) acc[q][c] = 0ULL;

#pragma unroll
    for (int chunk = 0; chunk < 4; chunk++) {
        __syncthreads();
#pragma unroll
        for (int l = 0; l < 8; l++) {
            int f = l * 256 + tid;
            int row = f >> 3, slot = f & 7;
            int gr = row0 + row;
            if (gr >= N_NODES) gr = N_NODES - 1;   // clamp; stores guarded
            __pipeline_memcpy_async(&xs[row * XS_STRIDE + slot * 4],
                                    &x[gr * 128 + chunk * 32 + slot * 4], 16);
        }
        __pipeline_commit();
        __pipeline_wait_prior(0);
        __syncthreads();

#pragma unroll
        for (int k4 = 0; k4 < 8; k4++) {
            int k4g = chunk * 8 + k4;
            const float* wbase = wt2 + k4g * 128 + cg * 4;
            ulonglong2 xv[4];
#pragma unroll
            for (int q = 0; q < 4; q++)
                xv[q] = *(const ulonglong2*)&xs[(rg + q * 64) * XS_STRIDE + k4 * 4];
#pragma unroll
            for (int ch = 0; ch < 2; ch++) {
                ulonglong2 wv[4];
#pragma unroll
                for (int c = 0; c < 4; c++)
                    wv[c] = *(const ulonglong2*)(wbase + (ch * 4 + c) * 16);
#pragma unroll
                for (int q = 0; q < 4; q++)
#pragma unroll
                    for (int c = 0; c < 4; c++)
                        ffma2(acc[q][ch * 4 + c], xv[q].x, wv[c].x);
#pragma unroll
                for (int q = 0; q < 4; q++)
#pragma unroll
                    for (int c = 0; c < 4; c++)
                        ffma2(acc[q][ch * 4 + c], xv[q].y, wv[c].y);
            }
        }
    }

#pragma unroll
    for (int q = 0; q < 4; q++) {
        int gr = row0 + rg + q * 64;
        if (gr < N_NODES) {
            float o[8];
#pragma unroll
            for (int c = 0; c < 8; c++) {
                float2 a = *(float2*)&acc[q][c];
                o[c] = a.x + a.y;
            }
            *(float4*)(&g_p[gr * 32 + cg * 8])     = make_float4(o[0], o[1], o[2], o[3]);
            *(float4*)(&g_p[gr * 32 + cg * 8 + 4]) = make_float4(o[4], o[5], o[6], o[7]);
        }
    }
}

__device__ __forceinline__ int warp_sum(int v) {
#pragma unroll
    for (int o = 16; o; o >>= 1) v += __shfl_xor_sync(0xffffffffu, v, o);
    return v;
}

// -------- single-pass exclusive scan over g_deg (decoupled lookback) --------
// Also restores g_deg to zero (replaces the separate memset launch).
__global__ void __launch_bounds__(512) k_scan() {
    __shared__ int s[512];
    __shared__ int s_prev;
    int b = blockIdx.x, t = threadIdx.x;
    int i = b * 512 + t;
    int v = (i < N_NODES) ? g_deg[i] : 0;
    if (i < N_NODES) g_deg[i] = 0;        // restore invariant for next call
    s[t] = v;
    __syncthreads();
#pragma unroll
    for (int off = 1; off < 512; off <<= 1) {
        int tv = (t >= off) ? s[t - off] : 0;
        __syncthreads();
        s[t] += tv;
        __syncthreads();
    }
    int incl = s[t];
    int blocksum = s[511];

    if (t == 0) {
        unsigned long long pkg = ((b == 0) ? (2ULL << 32) : (1ULL << 32))
                               | (unsigned int)blocksum;
        *(volatile unsigned long long*)&g_scanstate[b] = pkg;
    }

    if (t < 32) {
        int prefix = 0;
        int look = b - 1;
        while (look >= 0) {
            int idx = look - t;
            unsigned long long st = (idx >= 0)
                ? *(volatile unsigned long long*)&g_scanstate[idx]
                : (2ULL << 32);
            unsigned int flag = (unsigned int)(st >> 32);
            int val = (int)(st & 0xffffffffu);
            unsigned int nr = __ballot_sync(0xffffffffu, flag == 0u);
            unsigned int pm = __ballot_sync(0xffffffffu, flag == 2u);
            int firstP = pm ? (__ffs(pm) - 1) : 32;
            unsigned int below = (firstP < 32) ? ((1u << firstP) - 1u) : 0xffffffffu;
            if (firstP < 32 && (nr & below) == 0u) {
                int c = (t <= firstP) ? val : 0;
                prefix += warp_sum(c);
                break;
            } else if (nr == 0u) {
                prefix += warp_sum(val);
                look -= 32;
            }
        }
        if (t == 0) {
            s_prev = prefix;
            *(volatile unsigned long long*)&g_scanstate[b] =
                (2ULL << 32) | (unsigned int)(prefix + blocksum);
        }
    }
    __syncthreads();
    int base = s_prev;
    if (i < N_NODES)
        g_rowptr[i] = base + incl - v;
    if (b == NSCAN_BLOCKS - 1 && t == 511)
        g_rowptr[N_NODES] = base + incl;
}

// -------- fill: pos = rowptr[dst] + rank  (no atomics) --------
__global__ void k_fill(const int* __restrict__ src, const int* __restrict__ dst) {
    int e = blockIdx.x * blockDim.x + threadIdx.x;
    if (e * 4 < N_EDGES) {
        int4 s4 = ((const int4*)src)[e];
        int4 d4 = ((const int4*)dst)[e];
        int4 r4 = ((const int4*)g_rank)[e];
        g_eidx[__ldg(&g_rowptr[d4.x]) + r4.x] = s4.x;
        g_eidx[__ldg(&g_rowptr[d4.y]) + r4.y] = s4.y;
        g_eidx[__ldg(&g_rowptr[d4.z]) + r4.z] = s4.z;
        g_eidx[__ldg(&g_rowptr[d4.w]) + r4.w] = s4.w;
    }
}

// -------- layer-1 aggregate + combine + relu (8-wide unroll, 2 acc sets) ----
__global__ void __launch_bounds__(256) k_agg1(const float* __restrict__ b1) {
    int t = blockIdx.x * blockDim.x + threadIdx.x;
    int n = t >> 2;
    int fq = t & 3;
    if (n >= N_NODES) return;
    int beg = g_rowptr[n];
    int end = g_rowptr[n + 1];
    float4 acc = make_float4(0.f, 0.f, 0.f, 0.f);
    float4 acd = make_float4(0.f, 0.f, 0.f, 0.f);
    int i = beg;
    for (; i + 8 <= end; i += 8) {
        int s0 = g_eidx[i],     s1 = g_eidx[i + 1], s2 = g_eidx[i + 2], s3 = g_eidx[i + 3];
        int s4 = g_eidx[i + 4], s5 = g_eidx[i + 5], s6 = g_eidx[i + 6], s7 = g_eidx[i + 7];
        float4 v0 = *(const float4*)&g_p[s0 * 32 + 16 + fq * 4];
        float4 v1 = *(const float4*)&g_p[s1 * 32 + 16 + fq * 4];
        float4 v2 = *(const float4*)&g_p[s2 * 32 + 16 + fq * 4];
        float4 v3 = *(const float4*)&g_p[s3 * 32 + 16 + fq * 4];
        float4 v4 = *(const float4*)&g_p[s4 * 32 + 16 + fq * 4];
        float4 v5 = *(const float4*)&g_p[s5 * 32 + 16 + fq * 4];
        float4 v6 = *(const float4*)&g_p[s6 * 32 + 16 + fq * 4];
        float4 v7 = *(const float4*)&g_p[s7 * 32 + 16 + fq * 4];
        acc.x += (v0.x + v1.x) + (v2.x + v3.x);
        acc.y += (v0.y + v1.y) + (v2.y + v3.y);
        acc.z += (v0.z + v1.z) + (v2.z + v3.z);
        acc.w += (v0.w + v1.w) + (v2.w + v3.w);
        acd.x += (v4.x + v5.x) + (v6.x + v7.x);
        acd.y += (v4.y + v5.y) + (v6.y + v7.y);
        acd.z += (v4.z + v5.z) + (v6.z + v7.z);
        acd.w += (v4.w + v5.w) + (v6.w + v7.w);
    }
    for (; i < end; i++) {
        int s = g_eidx[i];
        float4 v = *(const float4*)&g_p[s * 32 + 16 + fq * 4];
        acc.x += v.x; acc.y += v.y; acc.z += v.z; acc.w += v.w;
    }
    acc.x += acd.x; acc.y += acd.y; acc.z += acd.z; acc.w += acd.w;
    float inv = 1.f / fmaxf((float)(end - beg), 1.f);
    float4 self = *(const float4*)&g_p[n * 32 + fq * 4];
    float4 bb = *(const float4*)&b1[fq * 4];
    float4 o;
    o.x = fmaxf(self.x + acc.x * inv + bb.x, 0.f);
    o.y = fmaxf(self.y + acc.y * inv + bb.y, 0.f);
    o.z = fmaxf(self.z + acc.z * inv + bb.z, 0.f);
    o.w = fmaxf(self.w + acc.w * inv + bb.w, 0.f);
    *(float4*)&g_h[n * 16 + fq * 4] = o;
}

// -------- fused layer-2 aggregate + output projection --------
__global__ void __launch_bounds__(256) k_agg2out(const float* __restrict__ wn2,
                                                 const float* __restrict__ ws2,
                                                 const float* __restrict__ b2,
                                                 float* __restrict__ out) {
    __shared__ float sw[2 * 640];
    __shared__ float sb[40];
    __shared__ float4 sh4[64 * 4];
    __shared__ float4 sm4[64 * 4];
    int t = threadIdx.x;
    for (int i = t; i < 640; i += 256) { sw[i] = ws2[i]; sw[640 + i] = wn2[i]; }
    if (t < 40) sb[t] = b2[t];

    int n0 = blockIdx.x * 64;
    int nl = t >> 2, fq = t & 3;
    int n = n0 + nl;
    float4 acc = make_float4(0.f, 0.f, 0.f, 0.f);
    float4 hv = make_float4(0.f, 0.f, 0.f, 0.f);
    if (n < N_NODES) {
        int beg = g_rowptr[n];
        int end = g_rowptr[n + 1];
        float4 acd = make_float4(0.f, 0.f, 0.f, 0.f);
        int i = beg;
        for (; i + 8 <= end; i += 8) {
            int s0 = g_eidx[i],     s1 = g_eidx[i + 1], s2 = g_eidx[i + 2], s3 = g_eidx[i + 3];
            int s4 = g_eidx[i + 4], s5 = g_eidx[i + 5], s6 = g_eidx[i + 6], s7 = g_eidx[i + 7];
            float4 v0 = *(const float4*)&g_h[s0 * 16 + fq * 4];
            float4 v1 = *(const float4*)&g_h[s1 * 16 + fq * 4];
            float4 v2 = *(const float4*)&g_h[s2 * 16 + fq * 4];
            float4 v3 = *(const float4*)&g_h[s3 * 16 + fq * 4];
            float4 v4 = *(const float4*)&g_h[s4 * 16 + fq * 4];
            float4 v5 = *(const float4*)&g_h[s5 * 16 + fq * 4];
            float4 v6 = *(const float4*)&g_h[s6 * 16 + fq * 4];
            float4 v7 = *(const float4*)&g_h[s7 * 16 + fq * 4];
            acc.x += (v0.x + v1.x) + (v2.x + v3.x);
            acc.y += (v0.y + v1.y) + (v2.y + v3.y);
            acc.z += (v0.z + v1.z) + (v2.z + v3.z);
            acc.w += (v0.w + v1.w) + (v2.w + v3.w);
            acd.x += (v4.x + v5.x) + (v6.x + v7.x);
            acd.y += (v4.y + v5.y) + (v6.y + v7.y);
            acd.z += (v4.z + v5.z) + (v6.z + v7.z);
            acd.w += (v4.w + v5.w) + (v6.w + v7.w);
        }
        for (; i < end; i++) {
            int s = g_eidx[i];
            float4 v = *(const float4*)&g_h[s * 16 + fq * 4];
            acc.x += v.x; acc.y += v.y; acc.z += v.z; acc.w += v.w;
        }
        acc.x += acd.x; acc.y += acd.y; acc.z += acd.z; acc.w += acd.w;
        float inv = 1.f / fmaxf((float)(end - beg), 1.f);
        acc.x *= inv; acc.y *= inv; acc.z *= inv; acc.w *= inv;
        hv = *(const float4*)&g_h[n * 16 + fq * 4];
    }
    sh4[nl * 4 + fq] = hv;
    sm4[nl * 4 + fq] = acc;
    __syncthreads();

    const float* shf = (const float*)sh4;
    const float* smf = (const float*)sm4;
#pragma unroll
    for (int o = t; o < 64 * 40; o += 256) {
        int n2 = o / 40, c = o % 40;
        int gn = n0 + n2;
        if (gn < N_NODES) {
            float a = sb[c];
#pragma unroll
            for (int k = 0; k < 16; k++)
                a += shf[n2 * 16 + k] * sw[k * 40 + c]
                   + smf[n2 * 16 + k] * sw[640 + k * 40 + c];
            out[gn * 40 + c] = a;
        }
    }
}

extern "C" void kernel_launch(void* const* d_in, const int* in_sizes, int n_in,
                              void* d_out, int out_size) {
    const float* x   = (const float*)d_in[0];
    const int*   src = (const int*)d_in[1];
    const int*   dst = (const int*)d_in[2];
    const float* wn1 = (const float*)d_in[3];
    const float* ws1 = (const float*)d_in[4];
    const float* b1  = (const float*)d_in[5];
    const float* wn2 = (const float*)d_in[6];
    const float* ws2 = (const float*)d_in[7];
    const float* b2  = (const float*)d_in[8];
    float* out = (float*)d_out;

    // NOTE: no memset — g_deg starts zero (module load) and k_scan re-zeroes it.
    k_gemm_count<<<GEMM_BLOCKS + EDGE_BLOCKS, 256>>>(x, wn1, ws1, dst);   // idx 0
    k_scan<<<NSCAN_BLOCKS, 512>>>();                                      // idx 1
    k_fill<<<EDGE_BLOCKS, 256>>>(src, dst);                               // idx 2
    k_agg1<<<(N_NODES * 4 + 255) / 256, 256>>>(b1);                       // idx 3
    k_agg2out<<<(N_NODES + 63) / 64, 256>>>(wn2, ws2, b2, out);           // idx 4
}

// round 10
// speedup vs baseline: 1.4124x; 1.0020x over previous
#include <cuda_runtime.h>
#include <cuda_bf16.h>
#include <cuda_fp16.h>
#include <cuda_pipeline.h>

#define N_NODES 100000
#define N_EDGES 1600000
#define NFEAT   128
#define NHID    16
#define NCLS    40
#define NSCAN_BLOCKS 196
#define GEMM_BLOCKS ((N_NODES + 255) / 256)          // 391
#define EDGE_BLOCKS ((N_EDGES / 4 + 255) / 256)      // 1563

// -------- scratch (device globals; zero-initialized at module load) --------
__device__ float  g_ps[N_NODES * 16];   // x @ w_self1  (fp32, read once per node)
__device__ __half g_pn[N_NODES * 16];   // x @ w_neigh1 (fp16, gathered per edge)
__device__ float  g_h [N_NODES * 16];   // layer-1 out fp32 (self path / projection)
__device__ __half g_hb[N_NODES * 16];   // layer-1 out fp16 (gathered per edge)
__device__ int    g_deg[N_NODES];       // INVARIANT: zero at entry/exit of each call
__device__ int    g_rowptr[N_NODES + 1];
__device__ int    g_rank[N_EDGES];      // edge's rank within its dst group
__device__ int    g_eidx[N_EDGES];      // src ids grouped by dst (CSR)
__device__ unsigned long long g_scanstate[NSCAN_BLOCKS];  // flag(hi32)|value(lo32)

// ===================== fused GEMM1 + degree count =====================
#define XS_STRIDE 36

__device__ __forceinline__ void ffma2(unsigned long long& acc,
                                      unsigned long long a,
                                      unsigned long long b) {
    asm("fma.rn.f32x2 %0, %1, %2, %0;" : "+l"(acc) : "l"(a), "l"(b));
}

__global__ void __launch_bounds__(256, 2) k_gemm_count(const float* __restrict__ x,
                                                       const float* __restrict__ wn1,
                                                       const float* __restrict__ ws1,
                                                       const int* __restrict__ dst) {
    __shared__ __align__(16) float xs[256 * XS_STRIDE];   // 36 KB
    __shared__ __align__(16) float wt2[4096];             // 16 KB
    int tid = threadIdx.x;

    if (blockIdx.x >= GEMM_BLOCKS) {
        // ---- count branch ----
        int cb = blockIdx.x - GEMM_BLOCKS;
        if (cb == 0 && tid < NSCAN_BLOCKS)
            *(volatile unsigned long long*)&g_scanstate[tid] = 0ULL;
        int e = cb * 256 + tid;
        if (e * 4 < N_EDGES) {
            int4 d = ((const int4*)dst)[e];
            int4 r;
            r.x = atomicAdd(&g_deg[d.x], 1);
            r.y = atomicAdd(&g_deg[d.y], 1);
            r.z = atomicAdd(&g_deg[d.z], 1);
            r.w = atomicAdd(&g_deg[d.w], 1);
            ((int4*)g_rank)[e] = r;
        }
        return;
    }

    // ---- gemm branch ----
    int row0 = blockIdx.x * 256;

    // pack weights: wt2[k4g*128 + c*16 + cg*4 + j] = W[k4g*4+j][cg*8+c]
    for (int i = tid; i < 4096; i += 256) {
        int j   = i & 3;
        int cg  = (i >> 2) & 3;
        int c   = (i >> 4) & 7;
        int k4g = i >> 7;
        int col = cg * 8 + c;
        int k   = k4g * 4 + j;
        wt2[i] = (col < 16) ? ws1[k * 16 + col] : wn1[k * 16 + (col - 16)];
    }

    int cg = tid & 3;        // col group (0..3), 8 cols each
    int rg = tid >> 2;       // row group (0..63), rows rg + q*64

    unsigned long long acc[4][8];
#pragma unroll
    for (int q = 0; q < 4; q++)
#pragma unroll
        for (int c = 0; c < 8; c++) acc[q][c] = 0ULL;

#pragma unroll
    for (int chunk = 0; chunk < 4; chunk++) {
        __syncthreads();
#pragma unroll
        for (int l = 0; l < 8; l++) {
            int f = l * 256 + tid;
            int row = f >> 3, slot = f & 7;
            int gr = row0 + row;
            if (gr >= N_NODES) gr = N_NODES - 1;   // clamp; stores guarded
            __pipeline_memcpy_async(&xs[row * XS_STRIDE + slot * 4],
                                    &x[gr * 128 + chunk * 32 + slot * 4], 16);
        }
        __pipeline_commit();
        __pipeline_wait_prior(0);
        __syncthreads();

#pragma unroll
        for (int k4 = 0; k4 < 8; k4++) {
            int k4g = chunk * 8 + k4;
            const float* wbase = wt2 + k4g * 128 + cg * 4;
            ulonglong2 xv[4];
#pragma unroll
            for (int q = 0; q < 4; q++)
                xv[q] = *(const ulonglong2*)&xs[(rg + q * 64) * XS_STRIDE + k4 * 4];
#pragma unroll
            for (int ch = 0; ch < 2; ch++) {
                ulonglong2 wv[4];
#pragma unroll
                for (int c = 0; c < 4; c++)
                    wv[c] = *(const ulonglong2*)(wbase + (ch * 4 + c) * 16);
#pragma unroll
                for (int q = 0; q < 4; q++)
#pragma unroll
                    for (int c = 0; c < 4; c++)
                        ffma2(acc[q][ch * 4 + c], xv[q].x, wv[c].x);
#pragma unroll
                for (int q = 0; q < 4; q++)
#pragma unroll
                    for (int c = 0; c < 4; c++)
                        ffma2(acc[q][ch * 4 + c], xv[q].y, wv[c].y);
            }
        }
    }

#pragma unroll
    for (int q = 0; q < 4; q++) {
        int gr = row0 + rg + q * 64;
        if (gr < N_NODES) {
            float o[8];
#pragma unroll
            for (int c = 0; c < 8; c++) {
                float2 a = *(float2*)&acc[q][c];
                o[c] = a.x + a.y;
            }
            if (cg < 2) {
                // self columns 0..15 -> fp32
                *(float4*)(&g_ps[gr * 16 + cg * 8])     = make_float4(o[0], o[1], o[2], o[3]);
                *(float4*)(&g_ps[gr * 16 + cg * 8 + 4]) = make_float4(o[4], o[5], o[6], o[7]);
            } else {
                // neighbor columns 16..31 -> fp16 (gather side)
                __half2 hh[4];
                hh[0] = __floats2half2_rn(o[0], o[1]);
                hh[1] = __floats2half2_rn(o[2], o[3]);
                hh[2] = __floats2half2_rn(o[4], o[5]);
                hh[3] = __floats2half2_rn(o[6], o[7]);
                *(uint4*)(&g_pn[gr * 16 + (cg - 2) * 8]) = *(uint4*)hh;
            }
        }
    }
}

__device__ __forceinline__ int warp_sum(int v) {
#pragma unroll
    for (int o = 16; o; o >>= 1) v += __shfl_xor_sync(0xffffffffu, v, o);
    return v;
}

// -------- single-pass exclusive scan over g_deg (decoupled lookback) --------
__global__ void __launch_bounds__(512) k_scan() {
    __shared__ int s[512];
    __shared__ int s_prev;
    int b = blockIdx.x, t = threadIdx.x;
    int i = b * 512 + t;
    int v = (i < N_NODES) ? g_deg[i] : 0;
    if (i < N_NODES) g_deg[i] = 0;        // restore invariant for next call
    s[t] = v;
    __syncthreads();
#pragma unroll
    for (int off = 1; off < 512; off <<= 1) {
        int tv = (t >= off) ? s[t - off] : 0;
        __syncthreads();
        s[t] += tv;
        __syncthreads();
    }
    int incl = s[t];
    int blocksum = s[511];

    if (t == 0) {
        unsigned long long pkg = ((b == 0) ? (2ULL << 32) : (1ULL << 32))
                               | (unsigned int)blocksum;
        *(volatile unsigned long long*)&g_scanstate[b] = pkg;
    }

    if (t < 32) {
        int prefix = 0;
        int look = b - 1;
        while (look >= 0) {
            int idx = look - t;
            unsigned long long st = (idx >= 0)
                ? *(volatile unsigned long long*)&g_scanstate[idx]
                : (2ULL << 32);
            unsigned int flag = (unsigned int)(st >> 32);
            int val = (int)(st & 0xffffffffu);
            unsigned int nr = __ballot_sync(0xffffffffu, flag == 0u);
            unsigned int pm = __ballot_sync(0xffffffffu, flag == 2u);
            int firstP = pm ? (__ffs(pm) - 1) : 32;
            unsigned int below = (firstP < 32) ? ((1u << firstP) - 1u) : 0xffffffffu;
            if (firstP < 32 && (nr & below) == 0u) {
                int c = (t <= firstP) ? val : 0;
                prefix += warp_sum(c);
                break;
            } else if (nr == 0u) {
                prefix += warp_sum(val);
                look -= 32;
            }
        }
        if (t == 0) {
            s_prev = prefix;
            *(volatile unsigned long long*)&g_scanstate[b] =
                (2ULL << 32) | (unsigned int)(prefix + blocksum);
        }
    }
    __syncthreads();
    int base = s_prev;
    if (i < N_NODES)
        g_rowptr[i] = base + incl - v;
    if (b == NSCAN_BLOCKS - 1 && t == 511)
        g_rowptr[N_NODES] = base + incl;
}

// -------- fill: pos = rowptr[dst] + rank  (no atomics) --------
__global__ void k_fill(const int* __restrict__ src, const int* __restrict__ dst) {
    int e = blockIdx.x * blockDim.x + threadIdx.x;
    if (e * 4 < N_EDGES) {
        int4 s4 = ((const int4*)src)[e];
        int4 d4 = ((const int4*)dst)[e];
        int4 r4 = ((const int4*)g_rank)[e];
        g_eidx[__ldg(&g_rowptr[d4.x]) + r4.x] = s4.x;
        g_eidx[__ldg(&g_rowptr[d4.y]) + r4.y] = s4.y;
        g_eidx[__ldg(&g_rowptr[d4.z]) + r4.z] = s4.z;
        g_eidx[__ldg(&g_rowptr[d4.w]) + r4.w] = s4.w;
    }
}

// convert 8 halves (uint4) and accumulate into 8 fp32 accs
__device__ __forceinline__ void addh8(float* a, uint4 u) {
    __half2 h0 = *(__half2*)&u.x;
    __half2 h1 = *(__half2*)&u.y;
    __half2 h2 = *(__half2*)&u.z;
    __half2 h3 = *(__half2*)&u.w;
    float2 f0 = __half22float2(h0);
    float2 f1 = __half22float2(h1);
    float2 f2 = __half22float2(h2);
    float2 f3 = __half22float2(h3);
    a[0] += f0.x; a[1] += f0.y;
    a[2] += f1.x; a[3] += f1.y;
    a[4] += f2.x; a[5] += f2.y;
    a[6] += f3.x; a[7] += f3.y;
}

// -------- layer-1 aggregate + combine + relu (2 lanes/node, fp16 gather) ----
__global__ void __launch_bounds__(256) k_agg1(const float* __restrict__ b1) {
    int t = blockIdx.x * blockDim.x + threadIdx.x;
    int n = t >> 1;
    int hf = t & 1;              // half: features hf*8 .. hf*8+7
    if (n >= N_NODES) return;
    int beg = g_rowptr[n];
    int end = g_rowptr[n + 1];
    float acc[8] = {0, 0, 0, 0, 0, 0, 0, 0};
    float acd[8] = {0, 0, 0, 0, 0, 0, 0, 0};
    int i = beg;
    for (; i + 4 <= end; i += 4) {
        int s0 = g_eidx[i], s1 = g_eidx[i + 1], s2 = g_eidx[i + 2], s3 = g_eidx[i + 3];
        uint4 u0 = *(const uint4*)&g_pn[s0 * 16 + hf * 8];
        uint4 u1 = *(const uint4*)&g_pn[s1 * 16 + hf * 8];
        uint4 u2 = *(const uint4*)&g_pn[s2 * 16 + hf * 8];
        uint4 u3 = *(const uint4*)&g_pn[s3 * 16 + hf * 8];
        addh8(acc, u0); addh8(acd, u1); addh8(acc, u2); addh8(acd, u3);
    }
    for (; i < end; i++) {
        int s = g_eidx[i];
        uint4 u = *(const uint4*)&g_pn[s * 16 + hf * 8];
        addh8(acc, u);
    }
#pragma unroll
    for (int j = 0; j < 8; j++) acc[j] += acd[j];

    float inv = 1.f / fmaxf((float)(end - beg), 1.f);
    float4 sa = *(const float4*)&g_ps[n * 16 + hf * 8];
    float4 sb = *(const float4*)&g_ps[n * 16 + hf * 8 + 4];
    float4 ba = *(const float4*)&b1[hf * 8];
    float4 bb = *(const float4*)&b1[hf * 8 + 4];
    float h[8];
    h[0] = fmaxf(sa.x + acc[0] * inv + ba.x, 0.f);
    h[1] = fmaxf(sa.y + acc[1] * inv + ba.y, 0.f);
    h[2] = fmaxf(sa.z + acc[2] * inv + ba.z, 0.f);
    h[3] = fmaxf(sa.w + acc[3] * inv + ba.w, 0.f);
    h[4] = fmaxf(sb.x + acc[4] * inv + bb.x, 0.f);
    h[5] = fmaxf(sb.y + acc[5] * inv + bb.y, 0.f);
    h[6] = fmaxf(sb.z + acc[6] * inv + bb.z, 0.f);
    h[7] = fmaxf(sb.w + acc[7] * inv + bb.w, 0.f);
    *(float4*)&g_h[n * 16 + hf * 8]     = make_float4(h[0], h[1], h[2], h[3]);
    *(float4*)&g_h[n * 16 + hf * 8 + 4] = make_float4(h[4], h[5], h[6], h[7]);
    __half2 hh[4];
    hh[0] = __floats2half2_rn(h[0], h[1]);
    hh[1] = __floats2half2_rn(h[2], h[3]);
    hh[2] = __floats2half2_rn(h[4], h[5]);
    hh[3] = __floats2half2_rn(h[6], h[7]);
    *(uint4*)&g_hb[n * 16 + hf * 8] = *(uint4*)hh;
}

// -------- fused layer-2 aggregate (fp16 gather) + output projection --------
// 256 threads = 128 nodes x 2 lanes; then 128x40 projection from smem.
__global__ void __launch_bounds__(256) k_agg2out(const float* __restrict__ wn2,
                                                 const float* __restrict__ ws2,
                                                 const float* __restrict__ b2,
                                                 float* __restrict__ out) {
    __shared__ float sw[2 * 640];     // ws2 | wn2 (k*40+c)
    __shared__ float sb[40];
    __shared__ float sh[128 * 16];    // h per node (fp32)
    __shared__ float sm[128 * 16];    // mean per node (fp32)
    int t = threadIdx.x;
    for (int i = t; i < 640; i += 256) { sw[i] = ws2[i]; sw[640 + i] = wn2[i]; }
    if (t < 40) sb[t] = b2[t];

    int n0 = blockIdx.x * 128;
    int nl = t >> 1, hf = t & 1;
    int n = n0 + nl;
    float acc[8] = {0, 0, 0, 0, 0, 0, 0, 0};
    if (n < N_NODES) {
        int beg = g_rowptr[n];
        int end = g_rowptr[n + 1];
        float acd[8] = {0, 0, 0, 0, 0, 0, 0, 0};
        int i = beg;
        for (; i + 4 <= end; i += 4) {
            int s0 = g_eidx[i], s1 = g_eidx[i + 1], s2 = g_eidx[i + 2], s3 = g_eidx[i + 3];
            uint4 u0 = *(const uint4*)&g_hb[s0 * 16 + hf * 8];
            uint4 u1 = *(const uint4*)&g_hb[s1 * 16 + hf * 8];
            uint4 u2 = *(const uint4*)&g_hb[s2 * 16 + hf * 8];
            uint4 u3 = *(const uint4*)&g_hb[s3 * 16 + hf * 8];
            addh8(acc, u0); addh8(acd, u1); addh8(acc, u2); addh8(acd, u3);
        }
        for (; i < end; i++) {
            int s = g_eidx[i];
            uint4 u = *(const uint4*)&g_hb[s * 16 + hf * 8];
            addh8(acc, u);
        }
        float inv = 1.f / fmaxf((float)(end - beg), 1.f);
#pragma unroll
        for (int j = 0; j < 8; j++) acc[j] = (acc[j] + acd[j]) * inv;

        float4 ha = *(const float4*)&g_h[n * 16 + hf * 8];
        float4 hb = *(const float4*)&g_h[n * 16 + hf * 8 + 4];
        *(float4*)&sh[nl * 16 + hf * 8]     = ha;
        *(float4*)&sh[nl * 16 + hf * 8 + 4] = hb;
    } else {
        *(float4*)&sh[nl * 16 + hf * 8]     = make_float4(0.f, 0.f, 0.f, 0.f);
        *(float4*)&sh[nl * 16 + hf * 8 + 4] = make_float4(0.f, 0.f, 0.f, 0.f);
    }
    *(float4*)&sm[nl * 16 + hf * 8]     = make_float4(acc[0], acc[1], acc[2], acc[3]);
    *(float4*)&sm[nl * 16 + hf * 8 + 4] = make_float4(acc[4], acc[5], acc[6], acc[7]);
    __syncthreads();

#pragma unroll
    for (int o = t; o < 128 * 40; o += 256) {
        int n2 = o / 40, c = o % 40;
        int gn = n0 + n2;
        if (gn < N_NODES) {
            float a = sb[c];
#pragma unroll
            for (int k = 0; k < 16; k++)
                a += sh[n2 * 16 + k] * sw[k * 40 + c]
                   + sm[n2 * 16 + k] * sw[640 + k * 40 + c];
            out[gn * 40 + c] = a;
        }
    }
}

extern "C" void kernel_launch(void* const* d_in, const int* in_sizes, int n_in,
                              void* d_out, int out_size) {
    const float* x   = (const float*)d_in[0];
    const int*   src = (const int*)d_in[1];
    const int*   dst = (const int*)d_in[2];
    const float* wn1 = (const float*)d_in[3];
    const float* ws1 = (const float*)d_in[4];
    const float* b1  = (const float*)d_in[5];
    const float* wn2 = (const float*)d_in[6];
    const float* ws2 = (const float*)d_in[7];
    const float* b2  = (const float*)d_in[8];
    float* out = (float*)d_out;

    k_gemm_count<<<GEMM_BLOCKS + EDGE_BLOCKS, 256>>>(x, wn1, ws1, dst);   // idx 0
    k_scan<<<NSCAN_BLOCKS, 512>>>();                                      // idx 1
    k_fill<<<EDGE_BLOCKS, 256>>>(src, dst);                               // idx 2
    k_agg1<<<(N_NODES * 2 + 255) / 256, 256>>>(b1);                       // idx 3 -> profiled
    k_agg2out<<<(N_NODES + 127) / 128, 256>>>(wn2, ws2, b2, out);         // idx 4
}